// round 13
// baseline (speedup 1.0000x reference)
#include <cuda_runtime.h>
#include <cuda_fp16.h>

#define NN 50000
typedef unsigned long long u64;
typedef unsigned int u32;

__device__ __align__(256) __half g_yh[(size_t)NN * 512];   // gate quads: [node][4u+t]
__device__ __align__(256) __half g_Wp[512 * 136];          // W_hh, no-shuffle perm, 272B stride
__device__ __align__(256) __half g_Wihp[512 * 136];        // W_ih, same perm
__device__ __align__(256) __half g_Wc[128 * 264];          // [j][ W_self(128) | W_neigh(128) ], 528B stride
__device__ __align__(256) float g_bp[512];                 // b_ih+b_hh, quad layout [4u+t]
__device__ __align__(256) float g_bsn[128];                // b_self+b_neigh

// ---- async copy ----
__device__ __forceinline__ void cp16(void* dst, const void* src) {
    unsigned sa = (unsigned)__cvta_generic_to_shared(dst);
    asm volatile("cp.async.cg.shared.global [%0],[%1],16;" :: "r"(sa), "l"(src) : "memory");
}
__device__ __forceinline__ void cp_commit() { asm volatile("cp.async.commit_group;" ::: "memory"); }
template <int W> __device__ __forceinline__ void cp_wait() {
    asm volatile("cp.async.wait_group %0;" :: "n"(W) : "memory");
}
// ---- fast activations ----
__device__ __forceinline__ float tanha(float x) {
    float r; asm("tanh.approx.f32 %0,%1;" : "=f"(r) : "f"(x)); return r;
}
__device__ __forceinline__ float sigt(float x) { return fmaf(tanha(0.5f * x), 0.5f, 0.5f); }
__device__ __forceinline__ u32 tanh2(u32 x) {
    u32 r; asm("tanh.approx.f16x2 %0,%1;" : "=r"(r) : "r"(x)); return r;
}
__device__ __forceinline__ u32 f2h2(float lo, float hi) {
    __half2 h = __floats2half2_rn(lo, hi); return *(u32*)&h;
}
__device__ __forceinline__ float2 h2f2(u32 v) { return __half22float2(*(__half2*)&v); }
__device__ __forceinline__ u32 hadd2u(u32 a, u32 b) {
    __half2 r = __hadd2(*(__half2*)&a, *(__half2*)&b); return *(u32*)&r;
}
__device__ __forceinline__ u32 hmul2u(u32 a, u32 b) {
    __half2 r = __hmul2(*(__half2*)&a, *(__half2*)&b); return *(u32*)&r;
}
__device__ __forceinline__ u32 hfma2u(u32 a, u32 b, u32 c) {
    __half2 r = __hfma2(*(__half2*)&a, *(__half2*)&b, *(__half2*)&c); return *(u32*)&r;
}

// ---- tensor-core (legacy mma.sync, baseline sm_100) ----
__device__ __forceinline__ u32 smem_u32(const void* p) {
    u32 a; asm("{ .reg .u64 t; cvta.to.shared.u64 t,%1; cvt.u32.u64 %0,t; }" : "=r"(a) : "l"(p)); return a;
}
__device__ __forceinline__ void ldmA(u32* r, u32 a) {
    asm volatile("ldmatrix.sync.aligned.m8n8.x4.shared.b16 {%0,%1,%2,%3},[%4];"
        : "=r"(r[0]), "=r"(r[1]), "=r"(r[2]), "=r"(r[3]) : "r"(a));
}
__device__ __forceinline__ void ldmB(u32* r, u32 a) {
    asm volatile("ldmatrix.sync.aligned.m8n8.x2.shared.b16 {%0,%1},[%2];"
        : "=r"(r[0]), "=r"(r[1]) : "r"(a));
}
__device__ __forceinline__ void mmaf16(float* d, const u32* a, const u32* b) {
    asm volatile("mma.sync.aligned.m16n8k16.row.col.f32.f16.f16.f32 "
        "{%0,%1,%2,%3},{%4,%5,%6,%7},{%8,%9},{%0,%1,%2,%3};"
        : "+f"(d[0]), "+f"(d[1]), "+f"(d[2]), "+f"(d[3])
        : "r"(a[0]), "r"(a[1]), "r"(a[2]), "r"(a[3]), "r"(b[0]), "r"(b[1]));
}

// fused smem (bytes): W region [139264] (reused: Wc[67584] | x[17408] | r[33792]) | A 2x17408 | sidx[4096]
#define WC_OFF 0
#define X_OFF  67584
#define R_OFF  84992
#define A_OFF  139264
#define ABUF   17408
#define SIDX_OFF 174080
#define LSTM_SMEM 178176
#define NODES 64
#define LTHREADS 512
// y2 smem: W[139264] | A x-tile [17408]
#define Y_A_OFF 139264
#define Y_SMEM  156672

// no-shuffle gate column permutation: unit u, type t -> column
__device__ __forceinline__ int gate_col(int u, int t) {
    return ((u >> 3) << 5) + (((((t >> 1) << 1) | ((u >> 2) & 1))) << 3) + ((u & 3) << 1) + (t & 1);
}

// ---- prep ----
__global__ void prep_kernel(const float* __restrict__ W_ih, const float* __restrict__ W_hh,
                            const float* __restrict__ W_self, const float* __restrict__ W_neigh,
                            const float* __restrict__ b_ih, const float* __restrict__ b_hh,
                            const float* __restrict__ b_self, const float* __restrict__ b_neigh) {
    int i = blockIdx.x * 256 + threadIdx.x;
    if (i < 512 * 128) {
        int g = i >> 7, k = i & 127;
        int t = g >> 7, u = g & 127;
        int nc = gate_col(u, t);
        g_Wp[nc * 136 + k]   = __float2half(W_hh[i]);
        g_Wihp[nc * 136 + k] = __float2half(W_ih[i]);
    }
    if (i < 128 * 256) {
        int j = i >> 8, k = i & 255;
        g_Wc[j * 264 + k] = __float2half(k < 128 ? W_self[j * 128 + k] : W_neigh[j * 128 + (k - 128)]);
    }
    if (i < 512) {
        int t = i >> 7, u = i & 127;
        g_bp[(u << 2) | t] = b_ih[i] + b_hh[i];
    }
    if (i < 128) g_bsn[i] = b_self[i] + b_neigh[i];
}

// stage 64 fp32 rows -> fp16 A tile, 272B stride (512 threads)
__device__ __forceinline__ void stage_x16(char* sb, int off, const float* __restrict__ x, int base, int tid) {
    int r = tid >> 3, cq = tid & 7, n = base + r;
    const float4* s4 = (const float4*)(x + (size_t)n * 128 + cq * 16);
    u32 h2v[8];
#pragma unroll
    for (int u = 0; u < 4; ++u) {
        float4 v = make_float4(0.f, 0.f, 0.f, 0.f);
        if (n < NN) v = s4[u];
        h2v[u * 2] = f2h2(v.x, v.y); h2v[u * 2 + 1] = f2h2(v.z, v.w);
    }
    *(uint4*)(sb + off + r * 272 + cq * 32)      = make_uint4(h2v[0], h2v[1], h2v[2], h2v[3]);
    *(uint4*)(sb + off + r * 272 + cq * 32 + 16) = make_uint4(h2v[4], h2v[5], h2v[6], h2v[7]);
}

// ---- y2: y = x @ W_ih^T + bias (mma, shuffle-free decode) ----
__global__ __launch_bounds__(LTHREADS, 1) void y2(const float* __restrict__ x) {
    extern __shared__ char sb[];
    u32 sbase = smem_u32(sb);
    const int tid = threadIdx.x, w = tid >> 5, lane = tid & 31;
    const int base = blockIdx.x * NODES;

#pragma unroll
    for (int i = 0; i < 17; ++i) { int c16 = i * LTHREADS + tid; cp16(sb + c16 * 16, (const char*)g_Wihp + c16 * 16); }
    cp_commit();
    stage_x16(sb, Y_A_OFF, x, base, tid);
    cp_wait<0>();
    __syncthreads();

    const int q = lane & 3, r = lane >> 2;

    u32 bfr[64];
    {
        const u32 aLaneB = sbase + (u32)(w * 32 + (lane & 7)) * 272 + (u32)((lane & 8) * 2);
#pragma unroll
        for (int kk = 0; kk < 8; ++kk)
#pragma unroll
            for (int nt = 0; nt < 4; ++nt)
                ldmB(&bfr[(kk * 4 + nt) * 2], aLaneB + (u32)(nt * 8) * 272 + (u32)(kk * 32));
    }

    const u32 aLaneA = sbase + Y_A_OFF + (u32)(lane & 15) * 272 + (u32)(lane & 16);
#pragma unroll 1
    for (int mt = 0; mt < 4; ++mt) {
        float D[4][4];
#pragma unroll
        for (int j = 0; j < 4; ++j) { D[j][0] = 0.f; D[j][1] = 0.f; D[j][2] = 0.f; D[j][3] = 0.f; }
        u32 amt = aLaneA + (u32)(mt * 16) * 272;
        u32 afr[2][4];
        ldmA(afr[0], amt);
#pragma unroll
        for (int kk = 0; kk < 8; ++kk) {
            if (kk < 7) ldmA(afr[(kk + 1) & 1], amt + (u32)((kk + 1) * 32));
#pragma unroll
            for (int nt = 0; nt < 4; ++nt)
                mmaf16(D[nt], afr[kk & 1], &bfr[(kk * 4 + nt) * 2]);
        }
#pragma unroll
        for (int p = 0; p < 2; ++p)
#pragma unroll
            for (int rs = 0; rs < 2; ++rs) {
                int u = w * 8 + p * 4 + q;
                float vi = D[p][rs * 2] , vf = D[p][rs * 2 + 1];
                float vg = D[2 + p][rs * 2], vo = D[2 + p][rs * 2 + 1];
                float4 b4 = *(const float4*)(g_bp + 4 * u);
                vi += b4.x; vf += b4.y; vg += b4.z; vo += b4.w;
                int gn = base + mt * 16 + r + rs * 8;
                u64 v = (u64)f2h2(vi, vf) | ((u64)f2h2(vg, vo) << 32);
                if (gn < NN) *(u64*)(g_yh + (size_t)gn * 512 + 4 * u) = v;
            }
    }
}

__device__ __forceinline__ void unpack_y(u64 raw, float& vi, float& vf, float& vg, float& vo) {
    float2 p = h2f2((u32)raw);
    float2 q = h2f2((u32)(raw >> 32));
    vi = p.x; vf = p.y; vg = q.x; vo = q.y;
}

// ---- fused LSTM + epilogue ----
__global__ __launch_bounds__(LTHREADS, 1) void lstm_epi(
    const int* __restrict__ nidx, const float* __restrict__ x,
    const float* __restrict__ g1, const float* __restrict__ bt1,
    const float* __restrict__ g3, const float* __restrict__ bt3, float* __restrict__ out) {
    extern __shared__ char sb[];
    u32 sbase = smem_u32(sb);
    const int tid = threadIdx.x, w = tid >> 5, lane = tid & 31;
    const int base = blockIdx.x * NODES;
    int* sidx = (int*)(sb + SIDX_OFF);

#pragma unroll
    for (int i = 0; i < 17; ++i) { int c16 = i * LTHREADS + tid; cp16(sb + c16 * 16, (const char*)g_Wp + c16 * 16); }
    cp_commit();
    for (int i = tid; i < NODES * 16; i += LTHREADS) {
        int n = base + (i >> 4);
        sidx[i] = (n < NN) ? nidx[n * 16 + (i & 15)] : 0;
    }

    const int q = lane & 3, r = lane >> 2;
    const int ubase = w * 8 + q;                       // + p*4
    float cst[16];
#pragma unroll
    for (int i = 0; i < 16; ++i) cst[i] = 0.f;

    cp_wait<0>();
    __syncthreads();

    // hoist W_hh fragments (W smem region dead afterwards)
    u32 bfr[64];
    {
        const u32 aLaneB = sbase + (u32)(w * 32 + (lane & 7)) * 272 + (u32)((lane & 8) * 2);
#pragma unroll
        for (int kk = 0; kk < 8; ++kk)
#pragma unroll
            for (int nt = 0; nt < 4; ++nt)
                ldmB(&bfr[(kk * 4 + nt) * 2], aLaneB + (u32)(nt * 8) * 272 + (u32)(kk * 32));
    }
    __syncthreads();  // all warps done reading W smem

    // overlap with t-loop: load Wc + stage x into dead W region
#pragma unroll
    for (int i = 0; i < 9; ++i) {
        int c = i * LTHREADS + tid;
        if (c < 4224) cp16(sb + WC_OFF + c * 16, (const char*)g_Wc + c * 16);
    }
    cp_commit();
    stage_x16(sb, X_OFF, x, base, tid);

    // f16x2 activation constants
    const u32 H05   = f2h2(0.5f, 0.5f);
    const u32 H1_05 = f2h2(1.0f, 0.5f);
    const u32 H0_05 = f2h2(0.0f, 0.5f);

    // ---- t = 0: gates = y only (f32 path, no D) ----
#pragma unroll 1
    for (int mt = 0; mt < 4; ++mt) {
#pragma unroll
        for (int p = 0; p < 2; ++p)
#pragma unroll
            for (int rs = 0; rs < 2; ++rs) {
                int u = ubase + p * 4;
                int row = mt * 16 + r + rs * 8;
                int rn = sidx[row * 16];
                float vi, vf, vg, vo;
                unpack_y(*(const u64*)(g_yh + (size_t)rn * 512 + 4 * u), vi, vf, vg, vo);
                float cc = sigt(vi) * tanha(vg);
                cst[mt * 4 + p * 2 + rs] = cc;
                float h = sigt(vo) * tanha(cc);
                __half bh = __float2half(h);
                asm volatile("st.shared.b16 [%0],%1;" :: "r"(sbase + A_OFF + (u32)row * 272 + (u32)u * 2),
                             "h"(*(unsigned short*)&bh) : "memory");
            }
    }

    u64 ybufA[4], ybufB[4];
#pragma unroll
    for (int p = 0; p < 2; ++p)
#pragma unroll
        for (int rs = 0; rs < 2; ++rs) {
            int rn = sidx[(r + rs * 8) * 16 + 1];
            ybufA[p * 2 + rs] = *(const u64*)(g_yh + (size_t)rn * 512 + 4 * (ubase + p * 4));
        }

    // ---- t = 1..15 ----
#pragma unroll 1
    for (int t = 1; t < 16; ++t) {
        __syncthreads();
        const u32 rdA = sbase + A_OFF + (u32)(((t - 1) & 1) * ABUF);
        const u32 wrA = sbase + A_OFF + (u32)((t & 1) * ABUF);
        const u32 aLaneA = rdA + (u32)(lane & 15) * 272 + (u32)(lane & 16);
#pragma unroll 1
        for (int mt = 0; mt < 4; ++mt) {
            u64* ycur = (mt & 1) ? ybufB : ybufA;
            u64* ynxt = (mt & 1) ? ybufA : ybufB;
            {
                int pmt = (mt < 3) ? (mt + 1) : 0;
                int pt = (mt < 3) ? t : (t + 1);
                if (pt < 16) {
#pragma unroll
                    for (int p = 0; p < 2; ++p)
#pragma unroll
                        for (int rs = 0; rs < 2; ++rs) {
                            int rn = sidx[(pmt * 16 + r + rs * 8) * 16 + pt];
                            ynxt[p * 2 + rs] = *(const u64*)(g_yh + (size_t)rn * 512 + 4 * (ubase + p * 4));
                        }
                }
            }

            float D[4][4];
#pragma unroll
            for (int j = 0; j < 4; ++j) { D[j][0] = 0.f; D[j][1] = 0.f; D[j][2] = 0.f; D[j][3] = 0.f; }

            u32 amt = aLaneA + (u32)(mt * 16) * 272;
            u32 afr[2][4];
            ldmA(afr[0], amt);
#pragma unroll
            for (int kk = 0; kk < 8; ++kk) {
                if (kk < 7) ldmA(afr[(kk + 1) & 1], amt + (u32)((kk + 1) * 32));
#pragma unroll
                for (int nt = 0; nt < 4; ++nt)
                    mmaf16(D[nt], afr[kk & 1], &bfr[(kk * 4 + nt) * 2]);
            }

            // f16x2 activation: 2 cells (rs=0,1) per p
#pragma unroll
            for (int p = 0; p < 2; ++p) {
                u64 y0 = ycur[p * 2 + 0], y1 = ycur[p * 2 + 1];
                u32 gif0 = hadd2u(f2h2(D[p][0], D[p][1]), (u32)y0);
                u32 gif1 = hadd2u(f2h2(D[p][2], D[p][3]), (u32)y1);
                u32 ggo0 = hadd2u(f2h2(D[2 + p][0], D[2 + p][1]), (u32)(y0 >> 32));
                u32 ggo1 = hadd2u(f2h2(D[2 + p][2], D[2 + p][3]), (u32)(y1 >> 32));
                u32 sif0 = hfma2u(tanh2(hmul2u(gif0, H05)), H05, H05);      // (sig_i, sig_f) cell0
                u32 sif1 = hfma2u(tanh2(hmul2u(gif1, H05)), H05, H05);      // cell1
                u32 tgo0 = hfma2u(tanh2(hmul2u(ggo0, H1_05)), H1_05, H0_05); // (tanh_g, sig_o) cell0
                u32 tgo1 = hfma2u(tanh2(hmul2u(ggo1, H1_05)), H1_05, H0_05); // cell1
                float2 a0 = h2f2(sif0), a1 = h2f2(sif1);
                float2 b0 = h2f2(tgo0), b1 = h2f2(tgo1);
                int ci = mt * 4 + p * 2;
                float cc0 = a0.y * cst[ci]     + a0.x * b0.x;
                float cc1 = a1.y * cst[ci + 1] + a1.x * b1.x;
                cst[ci] = cc0; cst[ci + 1] = cc1;
                float h0 = b0.y * tanha(cc0);
                float h1 = b1.y * tanha(cc1);
                int row0 = mt * 16 + r;
                u32 colb = (u32)(ubase + p * 4) * 2;
                __half bh0 = __float2half(h0), bh1 = __float2half(h1);
                asm volatile("st.shared.b16 [%0],%1;" :: "r"(wrA + (u32)row0 * 272 + colb),
                             "h"(*(unsigned short*)&bh0) : "memory");
                asm volatile("st.shared.b16 [%0],%1;" :: "r"(wrA + (u32)(row0 + 8) * 272 + colb),
                             "h"(*(unsigned short*)&bh1) : "memory");
            }
        }
    }
    cp_wait<0>();
    __syncthreads();   // final h visible (A buf 1), Wc + x staged

    // ---- epilogue GEMM: r = x@Ws^T + h@Wn^T + bsn ----
    const int mt = w & 3, nc = w >> 2;
    const u32 hA = sbase + A_OFF + ABUF;   // t=15 wrote buf 1
    float D[4][4];
#pragma unroll
    for (int j = 0; j < 4; ++j) { D[j][0] = 0.f; D[j][1] = 0.f; D[j][2] = 0.f; D[j][3] = 0.f; }
#pragma unroll 1
    for (int pass = 0; pass < 2; ++pass) {
        const u32 aLaneA = (pass ? hA : (sbase + X_OFF)) + (u32)((lane & 15) + mt * 16) * 272 + (u32)(lane & 16);
        u32 afr[2][4];
        ldmA(afr[0], aLaneA);
#pragma unroll
        for (int kk = 0; kk < 8; ++kk) {
            if (kk < 7) ldmA(afr[(kk + 1) & 1], aLaneA + (u32)((kk + 1) * 32));
#pragma unroll
            for (int nt = 0; nt < 4; ++nt) {
                u32 b2[2];
                ldmB(b2, sbase + WC_OFF + (u32)(nc * 32 + nt * 8 + (lane & 7)) * 528
                         + (u32)(pass * 256) + (u32)((lane & 8) * 2) + (u32)(kk * 32));
                mmaf16(D[nt], afr[kk & 1], b2);
            }
        }
    }
#pragma unroll
    for (int nt = 0; nt < 4; ++nt) {
        int c = nc * 32 + nt * 8 + (lane & 3) * 2;
        float2 bs = *(const float2*)(g_bsn + c);
        int r0 = mt * 16 + (lane >> 2);
        *(float2*)(sb + R_OFF + r0 * 528 + c * 4) = make_float2(D[nt][0] + bs.x, D[nt][1] + bs.y);
        *(float2*)(sb + R_OFF + (r0 + 8) * 528 + c * 4) = make_float2(D[nt][2] + bs.x, D[nt][3] + bs.y);
    }
    __syncthreads();

    // ---- LN -> leaky -> +x -> LN -> leaky; warp w: nodes w*4..w*4+3 ----
    float* sm_r = (float*)(sb + R_OFF);
    float4 gv1 = *(const float4*)(g1 + lane * 4), bv1 = *(const float4*)(bt1 + lane * 4);
    float4 gv3 = *(const float4*)(g3 + lane * 4), bv3 = *(const float4*)(bt3 + lane * 4);
#pragma unroll 1
    for (int qq = 0; qq < 4; ++qq) {
        int node = w * 4 + qq, n = base + node;
        if (n >= NN) break;
        float4 rv = *(float4*)(sm_r + node * 132 + lane * 4);
        float4 xv = *(const float4*)(x + (size_t)n * 128 + lane * 4);
        float s1 = rv.x + rv.y + rv.z + rv.w;
        float s2 = rv.x * rv.x + rv.y * rv.y + rv.z * rv.z + rv.w * rv.w;
#pragma unroll
        for (int mm = 16; mm > 0; mm >>= 1) { s1 += __shfl_xor_sync(~0u, s1, mm); s2 += __shfl_xor_sync(~0u, s2, mm); }
        float mu = s1 * 0.0078125f;
        float rs = rsqrtf(s2 * 0.0078125f - mu * mu + 1e-5f);
        float4 h;
        h.x = (rv.x - mu) * rs * gv1.x + bv1.x; h.y = (rv.y - mu) * rs * gv1.y + bv1.y;
        h.z = (rv.z - mu) * rs * gv1.z + bv1.z; h.w = (rv.w - mu) * rs * gv1.w + bv1.w;
        h.x = fmaxf(h.x, 0.01f * h.x) + xv.x; h.y = fmaxf(h.y, 0.01f * h.y) + xv.y;
        h.z = fmaxf(h.z, 0.01f * h.z) + xv.z; h.w = fmaxf(h.w, 0.01f * h.w) + xv.w;
        s1 = h.x + h.y + h.z + h.w;
        s2 = h.x * h.x + h.y * h.y + h.z * h.z + h.w * h.w;
#pragma unroll
        for (int mm = 16; mm > 0; mm >>= 1) { s1 += __shfl_xor_sync(~0u, s1, mm); s2 += __shfl_xor_sync(~0u, s2, mm); }
        mu = s1 * 0.0078125f;
        rs = rsqrtf(s2 * 0.0078125f - mu * mu + 1e-5f);
        float4 o;
        o.x = (h.x - mu) * rs * gv3.x + bv3.x; o.y = (h.y - mu) * rs * gv3.y + bv3.y;
        o.z = (h.z - mu) * rs * gv3.z + bv3.z; o.w = (h.w - mu) * rs * gv3.w + bv3.w;
        o.x = fmaxf(o.x, 0.01f * o.x); o.y = fmaxf(o.y, 0.01f * o.y);
        o.z = fmaxf(o.z, 0.01f * o.z); o.w = fmaxf(o.w, 0.01f * o.w);
        *(float4*)(out + (size_t)n * 128 + lane * 4) = o;
    }
}

extern "C" void kernel_launch(void* const* d_in, const int* in_sizes, int n_in,
                              void* d_out, int out_size) {
    const float* x       = (const float*)d_in[0];
    const int*   nidx    = (const int*)d_in[1];
    const float* W_self  = (const float*)d_in[2];
    const float* b_self  = (const float*)d_in[3];
    const float* W_neigh = (const float*)d_in[4];
    const float* b_neigh = (const float*)d_in[5];
    const float* W_ih    = (const float*)d_in[6];
    const float* W_hh    = (const float*)d_in[7];
    const float* b_ih    = (const float*)d_in[8];
    const float* b_hh    = (const float*)d_in[9];
    const float* g1      = (const float*)d_in[10];
    const float* bt1     = (const float*)d_in[11];
    const float* g3      = (const float*)d_in[12];
    const float* bt3     = (const float*)d_in[13];
    float* out = (float*)d_out;

    cudaFuncSetAttribute(y2,       cudaFuncAttributeMaxDynamicSharedMemorySize, Y_SMEM);
    cudaFuncSetAttribute(lstm_epi, cudaFuncAttributeMaxDynamicSharedMemorySize, LSTM_SMEM);

    int blk64 = (NN + NODES - 1) / NODES;  // 782
    prep_kernel<<<256, 256>>>(W_ih, W_hh, W_self, W_neigh, b_ih, b_hh, b_self, b_neigh);
    y2<<<blk64, LTHREADS, Y_SMEM>>>(x);
    lstm_epi<<<blk64, LTHREADS, LSTM_SMEM>>>(nidx, x, g1, bt1, g3, bt3, out);
}

// round 14
// speedup vs baseline: 1.1938x; 1.1938x over previous
#include <cuda_runtime.h>
#include <cuda_fp16.h>

#define NN 50000
typedef unsigned long long u64;
typedef unsigned int u32;

__device__ __align__(256) __half g_yh[(size_t)NN * 512];   // gate quads: [node][4u+t]
__device__ __align__(256) __half g_Wp[512 * 136];          // W_hh, no-shuffle perm, 272B stride
__device__ __align__(256) __half g_Wihp[512 * 136];        // W_ih, same perm
__device__ __align__(256) __half g_Wc[128 * 264];          // [j][ W_self(128) | W_neigh(128) ], 528B stride
__device__ __align__(256) float g_bp[512];                 // b_ih+b_hh, quad layout [4u+t]
__device__ __align__(256) float g_bsn[128];                // b_self+b_neigh

// ---- async copy ----
__device__ __forceinline__ void cp16(void* dst, const void* src) {
    unsigned sa = (unsigned)__cvta_generic_to_shared(dst);
    asm volatile("cp.async.cg.shared.global [%0],[%1],16;" :: "r"(sa), "l"(src) : "memory");
}
__device__ __forceinline__ void cp_commit() { asm volatile("cp.async.commit_group;" ::: "memory"); }
template <int W> __device__ __forceinline__ void cp_wait() {
    asm volatile("cp.async.wait_group %0;" :: "n"(W) : "memory");
}
// ---- fast activations ----
__device__ __forceinline__ float tanha(float x) {
    float r; asm("tanh.approx.f32 %0,%1;" : "=f"(r) : "f"(x)); return r;
}
__device__ __forceinline__ float sigt(float x) { return fmaf(tanha(0.5f * x), 0.5f, 0.5f); }

// ---- tensor-core (legacy mma.sync, baseline sm_100) ----
__device__ __forceinline__ u32 smem_u32(const void* p) {
    u32 a; asm("{ .reg .u64 t; cvta.to.shared.u64 t,%1; cvt.u32.u64 %0,t; }" : "=r"(a) : "l"(p)); return a;
}
__device__ __forceinline__ void ldmA(u32* r, u32 a) {
    asm volatile("ldmatrix.sync.aligned.m8n8.x4.shared.b16 {%0,%1,%2,%3},[%4];"
        : "=r"(r[0]), "=r"(r[1]), "=r"(r[2]), "=r"(r[3]) : "r"(a));
}
__device__ __forceinline__ void ldmB(u32* r, u32 a) {
    asm volatile("ldmatrix.sync.aligned.m8n8.x2.shared.b16 {%0,%1},[%2];"
        : "=r"(r[0]), "=r"(r[1]) : "r"(a));
}
__device__ __forceinline__ void mmaf16(float* d, const u32* a, const u32* b) {
    asm volatile("mma.sync.aligned.m16n8k16.row.col.f32.f16.f16.f32 "
        "{%0,%1,%2,%3},{%4,%5,%6,%7},{%8,%9},{%0,%1,%2,%3};"
        : "+f"(d[0]), "+f"(d[1]), "+f"(d[2]), "+f"(d[3])
        : "r"(a[0]), "r"(a[1]), "r"(a[2]), "r"(a[3]), "r"(b[0]), "r"(b[1]));
}

// fused smem (bytes): W region [139264] (reused: Wc[67584] | x[17408] | r[33792]) | A 2x17408 | sidx[4096]
#define WC_OFF 0
#define X_OFF  67584
#define R_OFF  84992
#define A_OFF  139264
#define ABUF   17408
#define SIDX_OFF 174080
#define LSTM_SMEM 178176
#define NODES 64
#define LTHREADS 512
// y2 smem: W[139264] | A x-tile [17408]
#define Y_A_OFF 139264
#define Y_SMEM  156672

// no-shuffle gate column permutation: unit u, type t -> column
__device__ __forceinline__ int gate_col(int u, int t) {
    return ((u >> 3) << 5) + (((((t >> 1) << 1) | ((u >> 2) & 1))) << 3) + ((u & 3) << 1) + (t & 1);
}

// ---- prep ----
__global__ void prep_kernel(const float* __restrict__ W_ih, const float* __restrict__ W_hh,
                            const float* __restrict__ W_self, const float* __restrict__ W_neigh,
                            const float* __restrict__ b_ih, const float* __restrict__ b_hh,
                            const float* __restrict__ b_self, const float* __restrict__ b_neigh) {
    int i = blockIdx.x * 256 + threadIdx.x;
    if (i < 512 * 128) {
        int g = i >> 7, k = i & 127;
        int t = g >> 7, u = g & 127;
        int nc = gate_col(u, t);
        g_Wp[nc * 136 + k]   = __float2half(W_hh[i]);
        g_Wihp[nc * 136 + k] = __float2half(W_ih[i]);
    }
    if (i < 128 * 256) {
        int j = i >> 8, k = i & 255;
        g_Wc[j * 264 + k] = __float2half(k < 128 ? W_self[j * 128 + k] : W_neigh[j * 128 + (k - 128)]);
    }
    if (i < 512) {
        int t = i >> 7, u = i & 127;
        g_bp[(u << 2) | t] = b_ih[i] + b_hh[i];
    }
    if (i < 128) g_bsn[i] = b_self[i] + b_neigh[i];
}

// stage 64 fp32 rows -> fp16 A tile, 272B stride (512 threads)
__device__ __forceinline__ void stage_x16(char* sb, int off, const float* __restrict__ x, int base, int tid) {
    int r = tid >> 3, cq = tid & 7, n = base + r;
    const float4* s4 = (const float4*)(x + (size_t)n * 128 + cq * 16);
    u32 h2v[8];
#pragma unroll
    for (int u = 0; u < 4; ++u) {
        float4 v = make_float4(0.f, 0.f, 0.f, 0.f);
        if (n < NN) v = s4[u];
        __half2 a = __floats2half2_rn(v.x, v.y), b = __floats2half2_rn(v.z, v.w);
        h2v[u * 2] = *(u32*)&a; h2v[u * 2 + 1] = *(u32*)&b;
    }
    *(uint4*)(sb + off + r * 272 + cq * 32)      = make_uint4(h2v[0], h2v[1], h2v[2], h2v[3]);
    *(uint4*)(sb + off + r * 272 + cq * 32 + 16) = make_uint4(h2v[4], h2v[5], h2v[6], h2v[7]);
}

// ---- y2: y = x @ W_ih^T + bias (mma, shuffle-free decode) ----
__global__ __launch_bounds__(LTHREADS, 1) void y2(const float* __restrict__ x) {
    extern __shared__ char sb[];
    u32 sbase = smem_u32(sb);
    const int tid = threadIdx.x, w = tid >> 5, lane = tid & 31;
    const int base = blockIdx.x * NODES;

#pragma unroll
    for (int i = 0; i < 17; ++i) { int c16 = i * LTHREADS + tid; cp16(sb + c16 * 16, (const char*)g_Wihp + c16 * 16); }
    cp_commit();
    stage_x16(sb, Y_A_OFF, x, base, tid);
    cp_wait<0>();
    __syncthreads();

    const int q = lane & 3, r = lane >> 2;

    u32 bfr[64];
    {
        const u32 aLaneB = sbase + (u32)(w * 32 + (lane & 7)) * 272 + (u32)((lane & 8) * 2);
#pragma unroll
        for (int kk = 0; kk < 8; ++kk)
#pragma unroll
            for (int nt = 0; nt < 4; ++nt)
                ldmB(&bfr[(kk * 4 + nt) * 2], aLaneB + (u32)(nt * 8) * 272 + (u32)(kk * 32));
    }

    const u32 aLaneA = sbase + Y_A_OFF + (u32)(lane & 15) * 272 + (u32)(lane & 16);
#pragma unroll 1
    for (int mt = 0; mt < 4; ++mt) {
        float D[4][4];
#pragma unroll
        for (int j = 0; j < 4; ++j) { D[j][0] = 0.f; D[j][1] = 0.f; D[j][2] = 0.f; D[j][3] = 0.f; }
        u32 amt = aLaneA + (u32)(mt * 16) * 272;
        u32 afr[2][4];
        ldmA(afr[0], amt);
#pragma unroll
        for (int kk = 0; kk < 8; ++kk) {
            if (kk < 7) ldmA(afr[(kk + 1) & 1], amt + (u32)((kk + 1) * 32));
#pragma unroll
            for (int nt = 0; nt < 4; ++nt)
                mmaf16(D[nt], afr[kk & 1], &bfr[(kk * 4 + nt) * 2]);
        }
#pragma unroll
        for (int p = 0; p < 2; ++p)
#pragma unroll
            for (int rs = 0; rs < 2; ++rs) {
                int u = w * 8 + p * 4 + q;
                float vi = D[p][rs * 2] , vf = D[p][rs * 2 + 1];
                float vg = D[2 + p][rs * 2], vo = D[2 + p][rs * 2 + 1];
                float4 b4 = *(const float4*)(g_bp + 4 * u);
                vi += b4.x; vf += b4.y; vg += b4.z; vo += b4.w;
                int gn = base + mt * 16 + r + rs * 8;
                __half2 pa = __floats2half2_rn(vi, vf), pb = __floats2half2_rn(vg, vo);
                u64 v = (u64)(*(u32*)&pa) | ((u64)(*(u32*)&pb) << 32);
                if (gn < NN) *(u64*)(g_yh + (size_t)gn * 512 + 4 * u) = v;
            }
    }
}

__device__ __forceinline__ void unpack_y(u64 raw, float& vi, float& vf, float& vg, float& vo) {
    u32 w0 = (u32)raw, w1 = (u32)(raw >> 32);
    float2 p = __half22float2(*(__half2*)&w0);
    float2 q = __half22float2(*(__half2*)&w1);
    vi = p.x; vf = p.y; vg = q.x; vo = q.y;
}

// ---- fused LSTM + epilogue, act pipelined one mt behind MMA ----
__global__ __launch_bounds__(LTHREADS, 1) void lstm_epi(
    const int* __restrict__ nidx, const float* __restrict__ x,
    const float* __restrict__ g1, const float* __restrict__ bt1,
    const float* __restrict__ g3, const float* __restrict__ bt3, float* __restrict__ out) {
    extern __shared__ char sb[];
    u32 sbase = smem_u32(sb);
    const int tid = threadIdx.x, w = tid >> 5, lane = tid & 31;
    const int base = blockIdx.x * NODES;
    int* sidx = (int*)(sb + SIDX_OFF);

#pragma unroll
    for (int i = 0; i < 17; ++i) { int c16 = i * LTHREADS + tid; cp16(sb + c16 * 16, (const char*)g_Wp + c16 * 16); }
    cp_commit();
    for (int i = tid; i < NODES * 16; i += LTHREADS) {
        int n = base + (i >> 4);
        sidx[i] = (n < NN) ? nidx[n * 16 + (i & 15)] : 0;
    }

    const int q = lane & 3, r = lane >> 2;
    const int ubase = w * 8 + q;                       // + p*4
    float cst[16];
#pragma unroll
    for (int i = 0; i < 16; ++i) cst[i] = 0.f;

    cp_wait<0>();
    __syncthreads();

    // hoist W_hh fragments (W smem region dead afterwards)
    u32 bfr[64];
    {
        const u32 aLaneB = sbase + (u32)(w * 32 + (lane & 7)) * 272 + (u32)((lane & 8) * 2);
#pragma unroll
        for (int kk = 0; kk < 8; ++kk)
#pragma unroll
            for (int nt = 0; nt < 4; ++nt)
                ldmB(&bfr[(kk * 4 + nt) * 2], aLaneB + (u32)(nt * 8) * 272 + (u32)(kk * 32));
    }
    __syncthreads();  // all warps done reading W smem

    // overlap with t-loop: load Wc + stage x into dead W region
#pragma unroll
    for (int i = 0; i < 9; ++i) {
        int c = i * LTHREADS + tid;
        if (c < 4224) cp16(sb + WC_OFF + c * 16, (const char*)g_Wc + c * 16);
    }
    cp_commit();
    stage_x16(sb, X_OFF, x, base, tid);

    // ---- t = 0: gates = y only ----
#pragma unroll 1
    for (int mt = 0; mt < 4; ++mt) {
#pragma unroll
        for (int p = 0; p < 2; ++p)
#pragma unroll
            for (int rs = 0; rs < 2; ++rs) {
                int u = ubase + p * 4;
                int row = mt * 16 + r + rs * 8;
                int rn = sidx[row * 16];
                float vi, vf, vg, vo;
                unpack_y(*(const u64*)(g_yh + (size_t)rn * 512 + 4 * u), vi, vf, vg, vo);
                float cc = sigt(vi) * tanha(vg);
                cst[mt * 4 + p * 2 + rs] = cc;
                float h = sigt(vo) * tanha(cc);
                __half bh = __float2half(h);
                asm volatile("st.shared.b16 [%0],%1;" :: "r"(sbase + A_OFF + (u32)row * 272 + (u32)u * 2),
                             "h"(*(unsigned short*)&bh) : "memory");
            }
    }

    // ISSUE: ldmA + 32 HMMA + y loads for tile MT at step T into DD/YY
#define ISSUE(MT, DD, YY, T)                                                        \
    {                                                                               \
        u32 amt = aLaneA + (u32)((MT) * 16) * 272;                                  \
        u32 afr[2][4];                                                              \
        ldmA(afr[0], amt);                                                          \
        _Pragma("unroll")                                                           \
        for (int kk = 0; kk < 8; ++kk) {                                            \
            if (kk < 7) ldmA(afr[(kk + 1) & 1], amt + (u32)((kk + 1) * 32));        \
            _Pragma("unroll")                                                       \
            for (int nt = 0; nt < 4; ++nt)                                          \
                mmaf16(DD[nt], afr[kk & 1], &bfr[(kk * 4 + nt) * 2]);               \
        }                                                                           \
        _Pragma("unroll")                                                           \
        for (int p = 0; p < 2; ++p)                                                 \
            _Pragma("unroll")                                                       \
            for (int rs = 0; rs < 2; ++rs) {                                        \
                int rn = sidx[((MT) * 16 + r + rs * 8) * 16 + (T)];                 \
                YY[p * 2 + rs] = *(const u64*)(g_yh + (size_t)rn * 512 + 4 * (ubase + p * 4)); \
            }                                                                       \
    }

    // ACT: activation for tile MT from DD/YY, write h into wrA
#define ACT(MT, DD, YY)                                                             \
    {                                                                               \
        _Pragma("unroll")                                                           \
        for (int p = 0; p < 2; ++p)                                                 \
            _Pragma("unroll")                                                       \
            for (int rs = 0; rs < 2; ++rs) {                                        \
                float vi = DD[p][rs * 2], vf = DD[p][rs * 2 + 1];                   \
                float vg = DD[2 + p][rs * 2], vo = DD[2 + p][rs * 2 + 1];           \
                float yi, yf, yg, yo;                                               \
                unpack_y(YY[p * 2 + rs], yi, yf, yg, yo);                           \
                vi += yi; vf += yf; vg += yg; vo += yo;                             \
                int ci = (MT) * 4 + p * 2 + rs;                                     \
                float cc = sigt(vf) * cst[ci] + sigt(vi) * tanha(vg);               \
                cst[ci] = cc;                                                       \
                float h = sigt(vo) * tanha(cc);                                     \
                int row = (MT) * 16 + r + rs * 8;                                   \
                __half bh = __float2half(h);                                        \
                asm volatile("st.shared.b16 [%0],%1;"                               \
                    :: "r"(wrA + (u32)row * 272 + (u32)(ubase + p * 4) * 2),        \
                       "h"(*(unsigned short*)&bh) : "memory");                      \
            }                                                                       \
    }

    // ---- t = 1..15: act lags one mt behind the MMA stream ----
#pragma unroll 1
    for (int t = 1; t < 16; ++t) {
        __syncthreads();
        const u32 rdA = sbase + A_OFF + (u32)(((t - 1) & 1) * ABUF);
        const u32 wrA = sbase + A_OFF + (u32)((t & 1) * ABUF);
        const u32 aLaneA = rdA + (u32)(lane & 15) * 272 + (u32)(lane & 16);

        float D0[4][4], D1[4][4];
        u64 y0[4], y1[4];
#pragma unroll
        for (int j = 0; j < 4; ++j) {
            D0[j][0] = D0[j][1] = D0[j][2] = D0[j][3] = 0.f;
            D1[j][0] = D1[j][1] = D1[j][2] = D1[j][3] = 0.f;
        }
        ISSUE(0, D0, y0, t);
        ISSUE(1, D1, y1, t);
        ACT(0, D0, y0);
#pragma unroll
        for (int j = 0; j < 4; ++j) { D0[j][0] = 0.f; D0[j][1] = 0.f; D0[j][2] = 0.f; D0[j][3] = 0.f; }
        ISSUE(2, D0, y0, t);
        ACT(1, D1, y1);
#pragma unroll
        for (int j = 0; j < 4; ++j) { D1[j][0] = 0.f; D1[j][1] = 0.f; D1[j][2] = 0.f; D1[j][3] = 0.f; }
        ISSUE(3, D1, y1, t);
        ACT(2, D0, y0);
        ACT(3, D1, y1);
    }
#undef ISSUE
#undef ACT
    cp_wait<0>();
    __syncthreads();   // final h visible (A buf 1), Wc + x staged

    // ---- epilogue GEMM: r = x@Ws^T + h@Wn^T + bsn ----
    const int mt = w & 3, nc = w >> 2;
    const u32 hA = sbase + A_OFF + ABUF;   // t=15 wrote buf 1
    float D[4][4];
#pragma unroll
    for (int j = 0; j < 4; ++j) { D[j][0] = 0.f; D[j][1] = 0.f; D[j][2] = 0.f; D[j][3] = 0.f; }
#pragma unroll 1
    for (int pass = 0; pass < 2; ++pass) {
        const u32 aLaneA = (pass ? hA : (sbase + X_OFF)) + (u32)((lane & 15) + mt * 16) * 272 + (u32)(lane & 16);
        u32 afr[2][4];
        ldmA(afr[0], aLaneA);
#pragma unroll
        for (int kk = 0; kk < 8; ++kk) {
            if (kk < 7) ldmA(afr[(kk + 1) & 1], aLaneA + (u32)((kk + 1) * 32));
#pragma unroll
            for (int nt = 0; nt < 4; ++nt) {
                u32 b2[2];
                ldmB(b2, sbase + WC_OFF + (u32)(nc * 32 + nt * 8 + (lane & 7)) * 528
                         + (u32)(pass * 256) + (u32)((lane & 8) * 2) + (u32)(kk * 32));
                mmaf16(D[nt], afr[kk & 1], b2);
            }
        }
    }
#pragma unroll
    for (int nt = 0; nt < 4; ++nt) {
        int c = nc * 32 + nt * 8 + (lane & 3) * 2;
        float2 bs = *(const float2*)(g_bsn + c);
        int r0 = mt * 16 + (lane >> 2);
        *(float2*)(sb + R_OFF + r0 * 528 + c * 4) = make_float2(D[nt][0] + bs.x, D[nt][1] + bs.y);
        *(float2*)(sb + R_OFF + (r0 + 8) * 528 + c * 4) = make_float2(D[nt][2] + bs.x, D[nt][3] + bs.y);
    }
    __syncthreads();

    // ---- LN -> leaky -> +x -> LN -> leaky; warp w: nodes w*4..w*4+3 ----
    float* sm_r = (float*)(sb + R_OFF);
    float4 gv1 = *(const float4*)(g1 + lane * 4), bv1 = *(const float4*)(bt1 + lane * 4);
    float4 gv3 = *(const float4*)(g3 + lane * 4), bv3 = *(const float4*)(bt3 + lane * 4);
#pragma unroll 1
    for (int qq = 0; qq < 4; ++qq) {
        int node = w * 4 + qq, n = base + node;
        if (n >= NN) break;
        float4 rv = *(float4*)(sm_r + node * 132 + lane * 4);
        float4 xv = *(const float4*)(x + (size_t)n * 128 + lane * 4);
        float s1 = rv.x + rv.y + rv.z + rv.w;
        float s2 = rv.x * rv.x + rv.y * rv.y + rv.z * rv.z + rv.w * rv.w;
#pragma unroll
        for (int mm = 16; mm > 0; mm >>= 1) { s1 += __shfl_xor_sync(~0u, s1, mm); s2 += __shfl_xor_sync(~0u, s2, mm); }
        float mu = s1 * 0.0078125f;
        float rs = rsqrtf(s2 * 0.0078125f - mu * mu + 1e-5f);
        float4 h;
        h.x = (rv.x - mu) * rs * gv1.x + bv1.x; h.y = (rv.y - mu) * rs * gv1.y + bv1.y;
        h.z = (rv.z - mu) * rs * gv1.z + bv1.z; h.w = (rv.w - mu) * rs * gv1.w + bv1.w;
        h.x = fmaxf(h.x, 0.01f * h.x) + xv.x; h.y = fmaxf(h.y, 0.01f * h.y) + xv.y;
        h.z = fmaxf(h.z, 0.01f * h.z) + xv.z; h.w = fmaxf(h.w, 0.01f * h.w) + xv.w;
        s1 = h.x + h.y + h.z + h.w;
        s2 = h.x * h.x + h.y * h.y + h.z * h.z + h.w * h.w;
#pragma unroll
        for (int mm = 16; mm > 0; mm >>= 1) { s1 += __shfl_xor_sync(~0u, s1, mm); s2 += __shfl_xor_sync(~0u, s2, mm); }
        mu = s1 * 0.0078125f;
        rs = rsqrtf(s2 * 0.0078125f - mu * mu + 1e-5f);
        float4 o;
        o.x = (h.x - mu) * rs * gv3.x + bv3.x; o.y = (h.y - mu) * rs * gv3.y + bv3.y;
        o.z = (h.z - mu) * rs * gv3.z + bv3.z; o.w = (h.w - mu) * rs * gv3.w + bv3.w;
        o.x = fmaxf(o.x, 0.01f * o.x); o.y = fmaxf(o.y, 0.01f * o.y);
        o.z = fmaxf(o.z, 0.01f * o.z); o.w = fmaxf(o.w, 0.01f * o.w);
        *(float4*)(out + (size_t)n * 128 + lane * 4) = o;
    }
}

extern "C" void kernel_launch(void* const* d_in, const int* in_sizes, int n_in,
                              void* d_out, int out_size) {
    const float* x       = (const float*)d_in[0];
    const int*   nidx    = (const int*)d_in[1];
    const float* W_self  = (const float*)d_in[2];
    const float* b_self  = (const float*)d_in[3];
    const float* W_neigh = (const float*)d_in[4];
    const float* b_neigh = (const float*)d_in[5];
    const float* W_ih    = (const float*)d_in[6];
    const float* W_hh    = (const float*)d_in[7];
    const float* b_ih    = (const float*)d_in[8];
    const float* b_hh    = (const float*)d_in[9];
    const float* g1      = (const float*)d_in[10];
    const float* bt1     = (const float*)d_in[11];
    const float* g3      = (const float*)d_in[12];
    const float* bt3     = (const float*)d_in[13];
    float* out = (float*)d_out;

    cudaFuncSetAttribute(y2,       cudaFuncAttributeMaxDynamicSharedMemorySize, Y_SMEM);
    cudaFuncSetAttribute(lstm_epi, cudaFuncAttributeMaxDynamicSharedMemorySize, LSTM_SMEM);

    int blk64 = (NN + NODES - 1) / NODES;  // 782
    prep_kernel<<<256, 256>>>(W_ih, W_hh, W_self, W_neigh, b_ih, b_hh, b_self, b_neigh);
    y2<<<blk64, LTHREADS, Y_SMEM>>>(x);
    lstm_epi<<<blk64, LTHREADS, LSTM_SMEM>>>(nidx, x, g1, bt1, g3, bt3, out);
}

// round 15
// speedup vs baseline: 1.3047x; 1.0929x over previous
#include <cuda_runtime.h>
#include <cuda_fp16.h>

#define NN 50000
typedef unsigned long long u64;
typedef unsigned int u32;

__device__ __align__(256) __half g_yh[(size_t)NN * 512];   // gate quads: [node][4u+t]
__device__ __align__(256) __half g_Wp[512 * 136];          // W_hh, no-shuffle perm, 272B stride
__device__ __align__(256) __half g_Wihp[512 * 136];        // W_ih, same perm
__device__ __align__(256) __half g_Wc[128 * 264];          // [j][ W_self(128) | W_neigh(128) ], 528B stride
__device__ __align__(256) float g_bp[512];                 // b_ih+b_hh, quad layout [4u+t]
__device__ __align__(256) float g_bsn[128];                // b_self+b_neigh

// ---- async copy ----
__device__ __forceinline__ void cp16(void* dst, const void* src) {
    unsigned sa = (unsigned)__cvta_generic_to_shared(dst);
    asm volatile("cp.async.cg.shared.global [%0],[%1],16;" :: "r"(sa), "l"(src) : "memory");
}
__device__ __forceinline__ void cp_commit() { asm volatile("cp.async.commit_group;" ::: "memory"); }
template <int W> __device__ __forceinline__ void cp_wait() {
    asm volatile("cp.async.wait_group %0;" :: "n"(W) : "memory");
}
// ---- fast activations ----
__device__ __forceinline__ float tanha(float x) {
    float r; asm("tanh.approx.f32 %0,%1;" : "=f"(r) : "f"(x)); return r;
}
__device__ __forceinline__ float sigt(float x) { return fmaf(tanha(0.5f * x), 0.5f, 0.5f); }
__device__ __forceinline__ float2 h2f2(u32 v) { return __half22float2(*(__half2*)&v); }
__device__ __forceinline__ u32 hadd2u(u32 a, u32 b) {
    __half2 r = __hadd2(*(__half2*)&a, *(__half2*)&b); return *(u32*)&r;
}

// ---- tensor-core (legacy mma.sync, baseline sm_100) ----
__device__ __forceinline__ u32 smem_u32(const void* p) {
    u32 a; asm("{ .reg .u64 t; cvta.to.shared.u64 t,%1; cvt.u32.u64 %0,t; }" : "=r"(a) : "l"(p)); return a;
}
__device__ __forceinline__ void ldmA(u32* r, u32 a) {
    asm volatile("ldmatrix.sync.aligned.m8n8.x4.shared.b16 {%0,%1,%2,%3},[%4];"
        : "=r"(r[0]), "=r"(r[1]), "=r"(r[2]), "=r"(r[3]) : "r"(a));
}
__device__ __forceinline__ void ldmB(u32* r, u32 a) {
    asm volatile("ldmatrix.sync.aligned.m8n8.x2.shared.b16 {%0,%1},[%2];"
        : "=r"(r[0]), "=r"(r[1]) : "r"(a));
}
__device__ __forceinline__ void mmaf16(float* d, const u32* a, const u32* b) {
    asm volatile("mma.sync.aligned.m16n8k16.row.col.f32.f16.f16.f32 "
        "{%0,%1,%2,%3},{%4,%5,%6,%7},{%8,%9},{%0,%1,%2,%3};"
        : "+f"(d[0]), "+f"(d[1]), "+f"(d[2]), "+f"(d[3])
        : "r"(a[0]), "r"(a[1]), "r"(a[2]), "r"(a[3]), "r"(b[0]), "r"(b[1]));
}
// fp16-accumulator variant (mainloop only)
__device__ __forceinline__ void mmah(u32* d, const u32* a, const u32* b) {
    asm volatile("mma.sync.aligned.m16n8k16.row.col.f16.f16.f16.f16 "
        "{%0,%1},{%2,%3,%4,%5},{%6,%7},{%0,%1};"
        : "+r"(d[0]), "+r"(d[1])
        : "r"(a[0]), "r"(a[1]), "r"(a[2]), "r"(a[3]), "r"(b[0]), "r"(b[1]));
}

// fused smem (bytes): W region [139264] (reused: Wc[67584] | x[17408] | r[33792]) | A 2x17408 | sidx[4096]
#define WC_OFF 0
#define X_OFF  67584
#define R_OFF  84992
#define A_OFF  139264
#define ABUF   17408
#define SIDX_OFF 174080
#define LSTM_SMEM 178176
#define NODES 64
#define LTHREADS 512
// y2 smem: W[139264] | A x-tile [17408]
#define Y_A_OFF 139264
#define Y_SMEM  156672

// no-shuffle gate column permutation: unit u, type t -> column
__device__ __forceinline__ int gate_col(int u, int t) {
    return ((u >> 3) << 5) + (((((t >> 1) << 1) | ((u >> 2) & 1))) << 3) + ((u & 3) << 1) + (t & 1);
}

// ---- prep ----
__global__ void prep_kernel(const float* __restrict__ W_ih, const float* __restrict__ W_hh,
                            const float* __restrict__ W_self, const float* __restrict__ W_neigh,
                            const float* __restrict__ b_ih, const float* __restrict__ b_hh,
                            const float* __restrict__ b_self, const float* __restrict__ b_neigh) {
    int i = blockIdx.x * 256 + threadIdx.x;
    if (i < 512 * 128) {
        int g = i >> 7, k = i & 127;
        int t = g >> 7, u = g & 127;
        int nc = gate_col(u, t);
        g_Wp[nc * 136 + k]   = __float2half(W_hh[i]);
        g_Wihp[nc * 136 + k] = __float2half(W_ih[i]);
    }
    if (i < 128 * 256) {
        int j = i >> 8, k = i & 255;
        g_Wc[j * 264 + k] = __float2half(k < 128 ? W_self[j * 128 + k] : W_neigh[j * 128 + (k - 128)]);
    }
    if (i < 512) {
        int t = i >> 7, u = i & 127;
        g_bp[(u << 2) | t] = b_ih[i] + b_hh[i];
    }
    if (i < 128) g_bsn[i] = b_self[i] + b_neigh[i];
}

// stage 64 fp32 rows -> fp16 A tile, 272B stride (512 threads)
__device__ __forceinline__ void stage_x16(char* sb, int off, const float* __restrict__ x, int base, int tid) {
    int r = tid >> 3, cq = tid & 7, n = base + r;
    const float4* s4 = (const float4*)(x + (size_t)n * 128 + cq * 16);
    u32 h2v[8];
#pragma unroll
    for (int u = 0; u < 4; ++u) {
        float4 v = make_float4(0.f, 0.f, 0.f, 0.f);
        if (n < NN) v = s4[u];
        __half2 a = __floats2half2_rn(v.x, v.y), b = __floats2half2_rn(v.z, v.w);
        h2v[u * 2] = *(u32*)&a; h2v[u * 2 + 1] = *(u32*)&b;
    }
    *(uint4*)(sb + off + r * 272 + cq * 32)      = make_uint4(h2v[0], h2v[1], h2v[2], h2v[3]);
    *(uint4*)(sb + off + r * 272 + cq * 32 + 16) = make_uint4(h2v[4], h2v[5], h2v[6], h2v[7]);
}

// ---- y2: y = x @ W_ih^T + bias (mma f32-accum, shuffle-free decode) ----
__global__ __launch_bounds__(LTHREADS, 1) void y2(const float* __restrict__ x) {
    extern __shared__ char sb[];
    u32 sbase = smem_u32(sb);
    const int tid = threadIdx.x, w = tid >> 5, lane = tid & 31;
    const int base = blockIdx.x * NODES;

#pragma unroll
    for (int i = 0; i < 17; ++i) { int c16 = i * LTHREADS + tid; cp16(sb + c16 * 16, (const char*)g_Wihp + c16 * 16); }
    cp_commit();
    stage_x16(sb, Y_A_OFF, x, base, tid);
    cp_wait<0>();
    __syncthreads();

    const int q = lane & 3, r = lane >> 2;

    u32 bfr[64];
    {
        const u32 aLaneB = sbase + (u32)(w * 32 + (lane & 7)) * 272 + (u32)((lane & 8) * 2);
#pragma unroll
        for (int kk = 0; kk < 8; ++kk)
#pragma unroll
            for (int nt = 0; nt < 4; ++nt)
                ldmB(&bfr[(kk * 4 + nt) * 2], aLaneB + (u32)(nt * 8) * 272 + (u32)(kk * 32));
    }

    const u32 aLaneA = sbase + Y_A_OFF + (u32)(lane & 15) * 272 + (u32)(lane & 16);
#pragma unroll 1
    for (int mt = 0; mt < 4; ++mt) {
        float D[4][4];
#pragma unroll
        for (int j = 0; j < 4; ++j) { D[j][0] = 0.f; D[j][1] = 0.f; D[j][2] = 0.f; D[j][3] = 0.f; }
        u32 amt = aLaneA + (u32)(mt * 16) * 272;
        u32 afr[2][4];
        ldmA(afr[0], amt);
#pragma unroll
        for (int kk = 0; kk < 8; ++kk) {
            if (kk < 7) ldmA(afr[(kk + 1) & 1], amt + (u32)((kk + 1) * 32));
#pragma unroll
            for (int nt = 0; nt < 4; ++nt)
                mmaf16(D[nt], afr[kk & 1], &bfr[(kk * 4 + nt) * 2]);
        }
#pragma unroll
        for (int p = 0; p < 2; ++p)
#pragma unroll
            for (int rs = 0; rs < 2; ++rs) {
                int u = w * 8 + p * 4 + q;
                float vi = D[p][rs * 2] , vf = D[p][rs * 2 + 1];
                float vg = D[2 + p][rs * 2], vo = D[2 + p][rs * 2 + 1];
                float4 b4 = *(const float4*)(g_bp + 4 * u);
                vi += b4.x; vf += b4.y; vg += b4.z; vo += b4.w;
                int gn = base + mt * 16 + r + rs * 8;
                __half2 pa = __floats2half2_rn(vi, vf), pb = __floats2half2_rn(vg, vo);
                u64 v = (u64)(*(u32*)&pa) | ((u64)(*(u32*)&pb) << 32);
                if (gn < NN) *(u64*)(g_yh + (size_t)gn * 512 + 4 * u) = v;
            }
    }
}

__device__ __forceinline__ void unpack_y(u64 raw, float& vi, float& vf, float& vg, float& vo) {
    float2 p = h2f2((u32)raw);
    float2 q = h2f2((u32)(raw >> 32));
    vi = p.x; vf = p.y; vg = q.x; vo = q.y;
}

// ---- fused LSTM + epilogue, act pipelined one mt behind MMA, fp16-accum mainloop ----
__global__ __launch_bounds__(LTHREADS, 1) void lstm_epi(
    const int* __restrict__ nidx, const float* __restrict__ x,
    const float* __restrict__ g1, const float* __restrict__ bt1,
    const float* __restrict__ g3, const float* __restrict__ bt3, float* __restrict__ out) {
    extern __shared__ char sb[];
    u32 sbase = smem_u32(sb);
    const int tid = threadIdx.x, w = tid >> 5, lane = tid & 31;
    const int base = blockIdx.x * NODES;
    int* sidx = (int*)(sb + SIDX_OFF);

#pragma unroll
    for (int i = 0; i < 17; ++i) { int c16 = i * LTHREADS + tid; cp16(sb + c16 * 16, (const char*)g_Wp + c16 * 16); }
    cp_commit();
    for (int i = tid; i < NODES * 16; i += LTHREADS) {
        int n = base + (i >> 4);
        sidx[i] = (n < NN) ? nidx[n * 16 + (i & 15)] : 0;
    }

    const int q = lane & 3, r = lane >> 2;
    const int ubase = w * 8 + q;                       // + p*4
    float cst[16];
#pragma unroll
    for (int i = 0; i < 16; ++i) cst[i] = 0.f;

    cp_wait<0>();
    __syncthreads();

    // hoist W_hh fragments (W smem region dead afterwards)
    u32 bfr[64];
    {
        const u32 aLaneB = sbase + (u32)(w * 32 + (lane & 7)) * 272 + (u32)((lane & 8) * 2);
#pragma unroll
        for (int kk = 0; kk < 8; ++kk)
#pragma unroll
            for (int nt = 0; nt < 4; ++nt)
                ldmB(&bfr[(kk * 4 + nt) * 2], aLaneB + (u32)(nt * 8) * 272 + (u32)(kk * 32));
    }
    __syncthreads();  // all warps done reading W smem

    // overlap with t-loop: load Wc + stage x into dead W region
#pragma unroll
    for (int i = 0; i < 9; ++i) {
        int c = i * LTHREADS + tid;
        if (c < 4224) cp16(sb + WC_OFF + c * 16, (const char*)g_Wc + c * 16);
    }
    cp_commit();
    stage_x16(sb, X_OFF, x, base, tid);

    // ---- t = 0: gates = y only ----
#pragma unroll 1
    for (int mt = 0; mt < 4; ++mt) {
#pragma unroll
        for (int p = 0; p < 2; ++p)
#pragma unroll
            for (int rs = 0; rs < 2; ++rs) {
                int u = ubase + p * 4;
                int row = mt * 16 + r + rs * 8;
                int rn = sidx[row * 16];
                float vi, vf, vg, vo;
                unpack_y(*(const u64*)(g_yh + (size_t)rn * 512 + 4 * u), vi, vf, vg, vo);
                float cc = sigt(vi) * tanha(vg);
                cst[mt * 4 + p * 2 + rs] = cc;
                float h = sigt(vo) * tanha(cc);
                __half bh = __float2half(h);
                asm volatile("st.shared.b16 [%0],%1;" :: "r"(sbase + A_OFF + (u32)row * 272 + (u32)u * 2),
                             "h"(*(unsigned short*)&bh) : "memory");
            }
    }

    // ISSUE: ldmA + 32 fp16-accum HMMA + y loads for tile MT at step T into DD/YY
#define ISSUE(MT, DD, YY, T)                                                        \
    {                                                                               \
        u32 amt = aLaneA + (u32)((MT) * 16) * 272;                                  \
        u32 afr[2][4];                                                              \
        ldmA(afr[0], amt);                                                          \
        _Pragma("unroll")                                                           \
        for (int kk = 0; kk < 8; ++kk) {                                            \
            if (kk < 7) ldmA(afr[(kk + 1) & 1], amt + (u32)((kk + 1) * 32));        \
            _Pragma("unroll")                                                       \
            for (int nt = 0; nt < 4; ++nt)                                          \
                mmah(DD[nt], afr[kk & 1], &bfr[(kk * 4 + nt) * 2]);                 \
        }                                                                           \
        _Pragma("unroll")                                                           \
        for (int p = 0; p < 2; ++p)                                                 \
            _Pragma("unroll")                                                       \
            for (int rs = 0; rs < 2; ++rs) {                                        \
                int rn = sidx[((MT) * 16 + r + rs * 8) * 16 + (T)];                 \
                YY[p * 2 + rs] = *(const u64*)(g_yh + (size_t)rn * 512 + 4 * (ubase + p * 4)); \
            }                                                                       \
    }

    // ACT: gates = fp16(D) + fp16(y) via HADD2, f32 activations, write h into wrA
#define ACT(MT, DD, YY)                                                             \
    {                                                                               \
        _Pragma("unroll")                                                           \
        for (int p = 0; p < 2; ++p)                                                 \
            _Pragma("unroll")                                                       \
            for (int rs = 0; rs < 2; ++rs) {                                        \
                u64 yv = YY[p * 2 + rs];                                            \
                u32 gif = hadd2u(DD[p][rs], (u32)yv);                               \
                u32 ggo = hadd2u(DD[2 + p][rs], (u32)(yv >> 32));                   \
                float2 fa = h2f2(gif), fb = h2f2(ggo);                              \
                int ci = (MT) * 4 + p * 2 + rs;                                     \
                float cc = sigt(fa.y) * cst[ci] + sigt(fa.x) * tanha(fb.x);         \
                cst[ci] = cc;                                                       \
                float h = sigt(fb.y) * tanha(cc);                                   \
                int row = (MT) * 16 + r + rs * 8;                                   \
                __half bh = __float2half(h);                                        \
                asm volatile("st.shared.b16 [%0],%1;"                               \
                    :: "r"(wrA + (u32)row * 272 + (u32)(ubase + p * 4) * 2),        \
                       "h"(*(unsigned short*)&bh) : "memory");                      \
            }                                                                       \
    }

    // ---- t = 1..15: act lags one mt behind the MMA stream ----
#pragma unroll 1
    for (int t = 1; t < 16; ++t) {
        __syncthreads();
        const u32 rdA = sbase + A_OFF + (u32)(((t - 1) & 1) * ABUF);
        const u32 wrA = sbase + A_OFF + (u32)((t & 1) * ABUF);
        const u32 aLaneA = rdA + (u32)(lane & 15) * 272 + (u32)(lane & 16);

        u32 D0[4][2], D1[4][2];
        u64 y0[4], y1[4];
#pragma unroll
        for (int j = 0; j < 4; ++j) {
            D0[j][0] = D0[j][1] = 0u;
            D1[j][0] = D1[j][1] = 0u;
        }
        ISSUE(0, D0, y0, t);
        ISSUE(1, D1, y1, t);
        ACT(0, D0, y0);
#pragma unroll
        for (int j = 0; j < 4; ++j) { D0[j][0] = 0u; D0[j][1] = 0u; }
        ISSUE(2, D0, y0, t);
        ACT(1, D1, y1);
#pragma unroll
        for (int j = 0; j < 4; ++j) { D1[j][0] = 0u; D1[j][1] = 0u; }
        ISSUE(3, D1, y1, t);
        ACT(2, D0, y0);
        ACT(3, D1, y1);
    }
#undef ISSUE
#undef ACT
    cp_wait<0>();
    __syncthreads();   // final h visible (A buf 1), Wc + x staged

    // ---- epilogue GEMM (f32 accum): r = x@Ws^T + h@Wn^T + bsn ----
    const int mt = w & 3, nc = w >> 2;
    const u32 hA = sbase + A_OFF + ABUF;   // t=15 wrote buf 1
    float D[4][4];
#pragma unroll
    for (int j = 0; j < 4; ++j) { D[j][0] = 0.f; D[j][1] = 0.f; D[j][2] = 0.f; D[j][3] = 0.f; }
#pragma unroll 1
    for (int pass = 0; pass < 2; ++pass) {
        const u32 aLaneA = (pass ? hA : (sbase + X_OFF)) + (u32)((lane & 15) + mt * 16) * 272 + (u32)(lane & 16);
        u32 afr[2][4];
        ldmA(afr[0], aLaneA);
#pragma unroll
        for (int kk = 0; kk < 8; ++kk) {
            if (kk < 7) ldmA(afr[(kk + 1) & 1], aLaneA + (u32)((kk + 1) * 32));
#pragma unroll
            for (int nt = 0; nt < 4; ++nt) {
                u32 b2[2];
                ldmB(b2, sbase + WC_OFF + (u32)(nc * 32 + nt * 8 + (lane & 7)) * 528
                         + (u32)(pass * 256) + (u32)((lane & 8) * 2) + (u32)(kk * 32));
                mmaf16(D[nt], afr[kk & 1], b2);
            }
        }
    }
#pragma unroll
    for (int nt = 0; nt < 4; ++nt) {
        int c = nc * 32 + nt * 8 + (lane & 3) * 2;
        float2 bs = *(const float2*)(g_bsn + c);
        int r0 = mt * 16 + (lane >> 2);
        *(float2*)(sb + R_OFF + r0 * 528 + c * 4) = make_float2(D[nt][0] + bs.x, D[nt][1] + bs.y);
        *(float2*)(sb + R_OFF + (r0 + 8) * 528 + c * 4) = make_float2(D[nt][2] + bs.x, D[nt][3] + bs.y);
    }
    __syncthreads();

    // ---- LN -> leaky -> +x -> LN -> leaky; warp w: nodes w*4..w*4+3 ----
    float* sm_r = (float*)(sb + R_OFF);
    float4 gv1 = *(const float4*)(g1 + lane * 4), bv1 = *(const float4*)(bt1 + lane * 4);
    float4 gv3 = *(const float4*)(g3 + lane * 4), bv3 = *(const float4*)(bt3 + lane * 4);
#pragma unroll 1
    for (int qq = 0; qq < 4; ++qq) {
        int node = w * 4 + qq, n = base + node;
        if (n >= NN) break;
        float4 rv = *(float4*)(sm_r + node * 132 + lane * 4);
        float4 xv = *(const float4*)(x + (size_t)n * 128 + lane * 4);
        float s1 = rv.x + rv.y + rv.z + rv.w;
        float s2 = rv.x * rv.x + rv.y * rv.y + rv.z * rv.z + rv.w * rv.w;
#pragma unroll
        for (int mm = 16; mm > 0; mm >>= 1) { s1 += __shfl_xor_sync(~0u, s1, mm); s2 += __shfl_xor_sync(~0u, s2, mm); }
        float mu = s1 * 0.0078125f;
        float rs = rsqrtf(s2 * 0.0078125f - mu * mu + 1e-5f);
        float4 h;
        h.x = (rv.x - mu) * rs * gv1.x + bv1.x; h.y = (rv.y - mu) * rs * gv1.y + bv1.y;
        h.z = (rv.z - mu) * rs * gv1.z + bv1.z; h.w = (rv.w - mu) * rs * gv1.w + bv1.w;
        h.x = fmaxf(h.x, 0.01f * h.x) + xv.x; h.y = fmaxf(h.y, 0.01f * h.y) + xv.y;
        h.z = fmaxf(h.z, 0.01f * h.z) + xv.z; h.w = fmaxf(h.w, 0.01f * h.w) + xv.w;
        s1 = h.x + h.y + h.z + h.w;
        s2 = h.x * h.x + h.y * h.y + h.z * h.z + h.w * h.w;
#pragma unroll
        for (int mm = 16; mm > 0; mm >>= 1) { s1 += __shfl_xor_sync(~0u, s1, mm); s2 += __shfl_xor_sync(~0u, s2, mm); }
        mu = s1 * 0.0078125f;
        rs = rsqrtf(s2 * 0.0078125f - mu * mu + 1e-5f);
        float4 o;
        o.x = (h.x - mu) * rs * gv3.x + bv3.x; o.y = (h.y - mu) * rs * gv3.y + bv3.y;
        o.z = (h.z - mu) * rs * gv3.z + bv3.z; o.w = (h.w - mu) * rs * gv3.w + bv3.w;
        o.x = fmaxf(o.x, 0.01f * o.x); o.y = fmaxf(o.y, 0.01f * o.y);
        o.z = fmaxf(o.z, 0.01f * o.z); o.w = fmaxf(o.w, 0.01f * o.w);
        *(float4*)(out + (size_t)n * 128 + lane * 4) = o;
    }
}

extern "C" void kernel_launch(void* const* d_in, const int* in_sizes, int n_in,
                              void* d_out, int out_size) {
    const float* x       = (const float*)d_in[0];
    const int*   nidx    = (const int*)d_in[1];
    const float* W_self  = (const float*)d_in[2];
    const float* b_self  = (const float*)d_in[3];
    const float* W_neigh = (const float*)d_in[4];
    const float* b_neigh = (const float*)d_in[5];
    const float* W_ih    = (const float*)d_in[6];
    const float* W_hh    = (const float*)d_in[7];
    const float* b_ih    = (const float*)d_in[8];
    const float* b_hh    = (const float*)d_in[9];
    const float* g1      = (const float*)d_in[10];
    const float* bt1     = (const float*)d_in[11];
    const float* g3      = (const float*)d_in[12];
    const float* bt3     = (const float*)d_in[13];
    float* out = (float*)d_out;

    cudaFuncSetAttribute(y2,       cudaFuncAttributeMaxDynamicSharedMemorySize, Y_SMEM);
    cudaFuncSetAttribute(lstm_epi, cudaFuncAttributeMaxDynamicSharedMemorySize, LSTM_SMEM);

    int blk64 = (NN + NODES - 1) / NODES;  // 782
    prep_kernel<<<256, 256>>>(W_ih, W_hh, W_self, W_neigh, b_ih, b_hh, b_self, b_neigh);
    y2<<<blk64, LTHREADS, Y_SMEM>>>(x);
    lstm_epi<<<blk64, LTHREADS, LSTM_SMEM>>>(nidx, x, g1, bt1, g3, bt3, out);
}